// round 15
// baseline (speedup 1.0000x reference)
#include <cuda_runtime.h>
#include <cuda_fp16.h>
#include <cstdint>

// Problem constants
#define CH      256
#define G_      16
#define RROWS   144
#define RED_CH  128
#define B_      8
#define HWD     64
#define HW      4096

// ---------------- mma.sync / async helpers -----------------------------------
__device__ __forceinline__ uint32_t smem_u32(const void* p) {
    uint32_t a;
    asm("{ .reg .u64 t; cvta.to.shared.u64 t, %1; cvt.u32.u64 %0, t; }" : "=r"(a) : "l"(p));
    return a;
}
__device__ __forceinline__ void ldm_x4(uint32_t& r0, uint32_t& r1, uint32_t& r2,
                                       uint32_t& r3, uint32_t addr) {
    asm volatile("ldmatrix.sync.aligned.m8n8.x4.shared.b16 {%0,%1,%2,%3}, [%4];"
        : "=r"(r0), "=r"(r1), "=r"(r2), "=r"(r3) : "r"(addr));
}
__device__ __forceinline__ void ldm_x4t(uint32_t& r0, uint32_t& r1, uint32_t& r2,
                                        uint32_t& r3, uint32_t addr) {
    asm volatile("ldmatrix.sync.aligned.m8n8.x4.trans.shared.b16 {%0,%1,%2,%3}, [%4];"
        : "=r"(r0), "=r"(r1), "=r"(r2), "=r"(r3) : "r"(addr));
}
__device__ __forceinline__ void mma_f16(float* c, const uint32_t* a, const uint32_t* b) {
    asm volatile("mma.sync.aligned.m16n8k16.row.col.f32.f16.f16.f32 "
        "{%0,%1,%2,%3}, {%4,%5,%6,%7}, {%8,%9}, {%0,%1,%2,%3};"
        : "+f"(c[0]), "+f"(c[1]), "+f"(c[2]), "+f"(c[3])
        : "r"(a[0]), "r"(a[1]), "r"(a[2]), "r"(a[3]), "r"(b[0]), "r"(b[1]));
}
__device__ __forceinline__ void fsplit2(float a, float b, uint32_t& hi, uint32_t& lo) {
    __half2 h = __floats2half2_rn(a, b);
    hi = *reinterpret_cast<uint32_t*>(&h);
    float ra = a - __half2float(__low2half(h));
    float rb = b - __half2float(__high2half(h));
    __half2 l = __floats2half2_rn(ra, rb);
    lo = *reinterpret_cast<uint32_t*>(&l);
}
__device__ __forceinline__ uint32_t fpack2(float a, float b) {
    __half2 h = __floats2half2_rn(a, b);
    return *reinterpret_cast<uint32_t*>(&h);
}
__device__ __forceinline__ void cp16(uint32_t sdst, const void* gsrc) {
    asm volatile("cp.async.cg.shared.global [%0], [%1], 16;" :: "r"(sdst), "l"(gsrc));
}
#define CP_COMMIT() asm volatile("cp.async.commit_group;" ::: "memory")
#define CP_WAIT0()  asm volatile("cp.async.wait_group 0;" ::: "memory")

// ---------------- device scratch (pre-split fp16) ----------------------------
__device__ uint4 g_WcH4[RROWS * 32];          // Wc ah: 144 x 256 fp16
__device__ uint4 g_WcL4[RROWS * 32];          // Wc al
__device__ uint4 g_KpH4[B_ * G_ * 64 * 24];   // A' ah per (b,g): 64 x 192, 384 B/row
__device__ uint4 g_KpL4[B_ * G_ * 64 * 24];   // A' al
__device__ float g_bc[RROWS];

// ---------------- kernel A: fuse weights, (row, col-quarter) CTAs ------------
__global__ __launch_bounds__(256) void fuse_weights(
        const float* __restrict__ W_reduce, const float* __restrict__ b_reduce,
        const float* __restrict__ W_span,   const float* __restrict__ b_span) {
    __shared__ float ws[RED_CH];
    __shared__ float2 ps[256];
    const int r   = blockIdx.x >> 2;       // 0..143
    const int cq  = blockIdx.x & 3;        // column quarter (32 col-pairs)
    const int tid = threadIdx.x;           // 256
    if (tid < RED_CH) ws[tid] = W_span[r * RED_CH + tid];
    __syncthreads();

    const int c2 = cq * 32 + (tid & 31);   // column pair 0..127
    const int o0 = (tid >> 5) * 16;        // 8 o-groups of 16
    const float2* Wr2 = (const float2*)W_reduce;
    float s0 = 0.f, s1 = 0.f;
    #pragma unroll
    for (int o = o0; o < o0 + 16; o++) {
        const float2 w = Wr2[o * 128 + c2];
        const float a = ws[o];
        s0 += a * w.x;
        s1 += a * w.y;
    }
    ps[tid] = make_float2(s0, s1);
    __syncthreads();

    if (tid < 32) {
        s0 = 0.f; s1 = 0.f;
        #pragma unroll
        for (int p = 0; p < 8; p++) {
            float2 t = ps[tid + p * 32];
            s0 += t.x; s1 += t.y;
        }
        uint32_t hi, lo;
        fsplit2(s0, s1, hi, lo);
        ((uint32_t*)g_WcH4)[r * 128 + cq * 32 + tid] = hi;
        ((uint32_t*)g_WcL4)[r * 128 + cq * 32 + tid] = lo;
    }
    if (cq == 0 && tid >= 32 && tid < 64) {
        const int L = tid - 32;
        float s = 0.f;
        #pragma unroll
        for (int o = L; o < RED_CH; o += 32) s += ws[o] * b_reduce[o];
        #pragma unroll
        for (int d = 16; d > 0; d >>= 1) s += __shfl_xor_sync(0xffffffffu, s, d);
        if (L == 0) g_bc[r] = s + b_span[r];
    }
    cudaTriggerProgrammaticLaunchCompletion();
}

// ---------------- kernel B: ker GEMM + fold, fp16 2-pass, PDL consumer -------
#define KSTR   144
#define KF_AH  0
#define KF_AL  20736
#define KF_B   41472          // x single fp16: 64 x 144B
#define KF_BC  50688
#define KF_SMEM (KF_BC + 576)

__global__ __launch_bounds__(384, 2) void ker_fold(const float* __restrict__ x) {
    extern __shared__ char smem[];
    const uint32_t sb = smem_u32(smem);
    float* sbc = (float*)(smem + KF_BC);
    const int i0 = blockIdx.x;
    const int b  = blockIdx.y;
    const int tid = threadIdx.x;
    const int wid = tid >> 5, lane = tid & 31;
    const int wm = wid % 3;           // M block of 48 rows
    const int wn = wid / 3;           // N block of 16 cols (0..3)
    const int r  = lane & 15, hh = lane >> 4;

    float acc[3][2][4];
    #pragma unroll
    for (int mt = 0; mt < 3; mt++)
        #pragma unroll
        for (int nt = 0; nt < 2; nt++)
            #pragma unroll
            for (int e = 0; e < 4; e++) acc[mt][nt][e] = 0.f;

    // prefetch kt=0 x slice into regs (fuse-independent; runs before grid sync)
    float4 breg[3];
    #pragma unroll
    for (int it = 0; it < 3; it++) {
        const int e = tid + 384 * it;
        if (e < 1024) {
            const int c = e >> 4, f = e & 15;
            breg[it] = *(const float4*)&x[((size_t)b * CH + c) * HW + i0 * HWD + f * 4];
        }
    }

    cudaGridDependencySynchronize();
    if (tid < RROWS) sbc[tid] = g_bc[tid];

    #pragma unroll 1
    for (int kt = 0; kt < 4; kt++) {
        __syncthreads();
        #pragma unroll
        for (int it = 0; it < 3; it++) {
            const int e = tid + 384 * it;
            const int row = e >> 3, q = e & 7;
            cp16(sb + KF_AH + row * KSTR + q * 16, &g_WcH4[row * 32 + kt * 8 + q]);
            cp16(sb + KF_AL + row * KSTR + q * 16, &g_WcL4[row * 32 + kt * 8 + q]);
        }
        CP_COMMIT();
        #pragma unroll
        for (int it = 0; it < 3; it++) {
            const int e = tid + 384 * it;
            if (e < 1024) {
                const int c = e >> 4, f = e & 15;
                const float4 v = breg[it];
                *(uint2*)(smem + KF_B + c * KSTR + f * 8) =
                    make_uint2(fpack2(v.x, v.y), fpack2(v.z, v.w));
            }
        }
        if (kt < 3) {
            #pragma unroll
            for (int it = 0; it < 3; it++) {
                const int e = tid + 384 * it;
                if (e < 1024) {
                    const int c = e >> 4, f = e & 15;
                    breg[it] = *(const float4*)&x[((size_t)b * CH + (kt + 1) * 64 + c) * HW + i0 * HWD + f * 4];
                }
            }
        }
        CP_WAIT0();
        __syncthreads();

        #pragma unroll
        for (int kk = 0; kk < 4; kk++) {
            uint32_t bh[4];
            const uint32_t bb = sb + KF_B + (kk * 16 + r) * KSTR + wn * 32 + hh * 16;
            ldm_x4t(bh[0], bh[1], bh[2], bh[3], bb);
            #pragma unroll
            for (int mt = 0; mt < 3; mt++) {
                uint32_t ah[4], al[4];
                const uint32_t ab = sb + KF_AH + (wm * 48 + mt * 16 + r) * KSTR + kk * 32 + hh * 16;
                ldm_x4(ah[0], ah[1], ah[2], ah[3], ab);
                ldm_x4(al[0], al[1], al[2], al[3], ab + (KF_AL - KF_AH));
                #pragma unroll
                for (int nt = 0; nt < 2; nt++) {
                    mma_f16(acc[mt][nt], ah, &bh[2 * nt]);
                    mma_f16(acc[mt][nt], al, &bh[2 * nt]);
                }
            }
        }
    }

    // ---- spill ker (+bias) to smem fp32 [144][68] ---------------------------
    __syncthreads();
    float* Ys = (float*)smem;
    {
        const int gq = lane >> 2;
        const int cb = (lane & 3) * 2;
        #pragma unroll
        for (int mt = 0; mt < 3; mt++) {
            const int row = wm * 48 + mt * 16 + gq;
            const float b0 = sbc[row], b1 = sbc[row + 8];
            #pragma unroll
            for (int nt = 0; nt < 2; nt++) {
                const int col = wn * 16 + nt * 8 + cb;
                *(float2*)&Ys[row * 68 + col]       = make_float2(acc[mt][nt][0] + b0, acc[mt][nt][1] + b0);
                *(float2*)&Ys[(row + 8) * 68 + col] = make_float2(acc[mt][nt][2] + b1, acc[mt][nt][3] + b1);
            }
        }
    }
    __syncthreads();

    // ---- fold over ki, write A' transposed fp16-split -----------------------
    if (tid < 256) {
        const int g  = tid >> 4;
        const int ms = (tid & 15) * 4;
        const size_t arow = ((size_t)(b * G_ + g) * 64 + i0) * 384;
        #pragma unroll
        for (int kj = 0; kj < 3; kj++) {
            const float* y1 = Ys + (g * 9 + 3 + kj) * 68;
            const float* y0 = Ys + (g * 9 + kj) * 68;
            const float* y2 = Ys + (g * 9 + 6 + kj) * 68;
            float v[4];
            #pragma unroll
            for (int mm = 0; mm < 4; mm++) {
                const int m = ms + mm;
                float t = y1[m];
                if (m < 63) t += y0[m + 1];
                if (m > 0)  t += y2[m - 1];
                v[mm] = t;
            }
            uint32_t h0, l0, h1, l1;
            fsplit2(v[0], v[1], h0, l0);
            fsplit2(v[2], v[3], h1, l1);
            const uint32_t cb2 = (kj * 64 + ms) * 2;
            *(uint2*)((char*)g_KpH4 + arow + cb2) = make_uint2(h0, h1);
            *(uint2*)((char*)g_KpL4 + arow + cb2) = make_uint2(l0, l1);
        }
    }
    cudaTriggerProgrammaticLaunchCompletion();
}

// ---------------- kernel C: shifted-B GEMM, double-buffered B', PDL ----------
#define IA_STR  400
#define I_AH    0
#define I_AL    25600
#define I_B0    51200          // B' buffer 0: 192 x 144B
#define I_B1    78848          // B' buffer 1
#define SMEM_INV 106496

__global__ __launch_bounds__(256, 2) void inv_mma(const float* __restrict__ x,
                                                  float* __restrict__ out) {
    extern __shared__ char smem[];
    const uint32_t sb = smem_u32(smem);
    const int cq = blockIdx.x, g = blockIdx.y, b = blockIdx.z;
    const int tid  = threadIdx.x;
    const int wid  = tid >> 5, lane = tid & 31;
    const int wm   = wid & 3;          // i quadrant (16 rows)
    const int wn   = wid >> 2;         // j half (32 cols)
    const int ch0  = g * 16 + cq * 4;
    const float* xbase = x + ((size_t)(b * CH) + ch0) * HW;

    int mArr[4], j0Arr[4];
    #pragma unroll
    for (int it = 0; it < 4; it++) {
        const int e = tid + 256 * it;
        mArr[it] = e >> 4;
        j0Arr[it] = (e & 15) << 2;
    }

    // prefetch x(channel 0) — independent of ker_fold
    float4 v[4]; float am1[4], a4[4];
    #pragma unroll
    for (int it = 0; it < 4; it++) {
        const float* row = xbase + mArr[it] * 64;
        v[it]  = *(const float4*)&row[j0Arr[it]];
        am1[it] = (j0Arr[it] > 0)  ? row[j0Arr[it] - 1] : 0.f;
        a4[it]  = (j0Arr[it] < 60) ? row[j0Arr[it] + 4] : 0.f;
    }

    cudaGridDependencySynchronize();
    {
        const uint4* KH = g_KpH4 + (size_t)(b * G_ + g) * 1536;
        const uint4* KL = g_KpL4 + (size_t)(b * G_ + g) * 1536;
        #pragma unroll
        for (int it = 0; it < 6; it++) {
            const int e = tid + 256 * it;
            const int row = e / 24, q = e - row * 24;
            cp16(sb + I_AH + row * IA_STR + q * 16, KH + e);
            cp16(sb + I_AL + row * IA_STR + q * 16, KL + e);
        }
        CP_COMMIT();
    }

    // ---- build B'(0) into buf0; prefetch x(1) -------------------------------
    #pragma unroll
    for (int it = 0; it < 4; it++) {
        const int m = mArr[it], j0 = j0Arr[it];
        uint32_t p0 = fpack2(am1[it], v[it].x);
        uint32_t p1 = fpack2(v[it].x, v[it].y);
        uint32_t p2 = fpack2(v[it].y, v[it].z);
        uint32_t p3 = fpack2(v[it].z, v[it].w);
        uint32_t p4 = fpack2(v[it].w, a4[it]);
        const uint32_t cbyte = j0 * 2;
        *(uint2*)(smem + I_B0 + m * 144 + cbyte)         = make_uint2(p0, p2);
        *(uint2*)(smem + I_B0 + (64 + m) * 144 + cbyte)  = make_uint2(p1, p3);
        *(uint2*)(smem + I_B0 + (128 + m) * 144 + cbyte) = make_uint2(p2, p4);
    }
    {
        const float* xn = xbase + HW;
        #pragma unroll
        for (int it = 0; it < 4; it++) {
            const float* row = xn + mArr[it] * 64;
            v[it]  = *(const float4*)&row[j0Arr[it]];
            am1[it] = (j0Arr[it] > 0)  ? row[j0Arr[it] - 1] : 0.f;
            a4[it]  = (j0Arr[it] < 60) ? row[j0Arr[it] + 4] : 0.f;
        }
    }
    CP_WAIT0();
    __syncthreads();

    const int r  = lane & 15;
    const int hh = lane >> 4;
    const int gq = lane >> 2, cb = (lane & 3) * 2;
    const int i0 = wm * 16 + gq;

    #pragma unroll 1
    for (int cc = 0; cc < 4; cc++) {
        const uint32_t bufR = (cc & 1) ? I_B1 : I_B0;   // MMA reads this
        const uint32_t bufW = (cc & 1) ? I_B0 : I_B1;   // build writes next
        // ---- build B'(cc+1) into the other buffer (overlaps with MMA) --------
        if (cc < 3) {
            #pragma unroll
            for (int it = 0; it < 4; it++) {
                const int m = mArr[it], j0 = j0Arr[it];
                uint32_t p0 = fpack2(am1[it], v[it].x);
                uint32_t p1 = fpack2(v[it].x, v[it].y);
                uint32_t p2 = fpack2(v[it].y, v[it].z);
                uint32_t p3 = fpack2(v[it].z, v[it].w);
                uint32_t p4 = fpack2(v[it].w, a4[it]);
                const uint32_t cbyte = j0 * 2;
                *(uint2*)(smem + bufW + m * 144 + cbyte)         = make_uint2(p0, p2);
                *(uint2*)(smem + bufW + (64 + m) * 144 + cbyte)  = make_uint2(p1, p3);
                *(uint2*)(smem + bufW + (128 + m) * 144 + cbyte) = make_uint2(p2, p4);
            }
        }
        // ---- prefetch x(cc+2) --------------------------------------------------
        if (cc < 2) {
            const float* xn = xbase + (size_t)(cc + 2) * HW;
            #pragma unroll
            for (int it = 0; it < 4; it++) {
                const float* row = xn + mArr[it] * 64;
                v[it]  = *(const float4*)&row[j0Arr[it]];
                am1[it] = (j0Arr[it] > 0)  ? row[j0Arr[it] - 1] : 0.f;
                a4[it]  = (j0Arr[it] < 60) ? row[j0Arr[it] + 4] : 0.f;
            }
        }

        // ---- K=192 mma from bufR, fp16 2-pass ---------------------------------
        float acc[4][4];
        #pragma unroll
        for (int nt = 0; nt < 4; nt++)
            #pragma unroll
            for (int e = 0; e < 4; e++) acc[nt][e] = 0.f;

        #pragma unroll
        for (int k = 0; k < 12; k++) {
            uint32_t ah[4], al[4];
            const uint32_t abase = sb + I_AH + (wm * 16 + r) * IA_STR + k * 32 + hh * 16;
            ldm_x4(ah[0], ah[1], ah[2], ah[3], abase);
            ldm_x4(al[0], al[1], al[2], al[3], abase + (I_AL - I_AH));
            uint32_t bh[4][2];
            #pragma unroll
            for (int ntp = 0; ntp < 2; ntp++) {
                const uint32_t bb = sb + bufR + (k * 16 + r) * 144 + wn * 64 + ntp * 32 + hh * 16;
                ldm_x4t(bh[2*ntp][0], bh[2*ntp][1], bh[2*ntp+1][0], bh[2*ntp+1][1], bb);
            }
            #pragma unroll
            for (int nt = 0; nt < 4; nt++) {
                mma_f16(acc[nt], ah, bh[nt]);
                mma_f16(acc[nt], al, bh[nt]);
            }
        }

        // ---- direct store -------------------------------------------------------
        float* op = out + ((size_t)(b * CH) + ch0 + cc) * HW;
        #pragma unroll
        for (int nt = 0; nt < 4; nt++) {
            const int j = wn * 32 + nt * 8 + cb;
            *(float2*)&op[i0 * 64 + j]       = make_float2(acc[nt][0], acc[nt][1]);
            *(float2*)&op[(i0 + 8) * 64 + j] = make_float2(acc[nt][2], acc[nt][3]);
        }
        if (cc < 3) __syncthreads();
    }
}

// ---------------- launch ------------------------------------------------------
static void launch_pdl(const void* fn, dim3 grid, dim3 block, size_t smem,
                       void** args) {
    cudaLaunchAttribute attr;
    attr.id = cudaLaunchAttributeProgrammaticStreamSerialization;
    attr.val.programmaticStreamSerializationAllowed = 1;
    cudaLaunchConfig_t cfg{};
    cfg.gridDim = grid;
    cfg.blockDim = block;
    cfg.dynamicSmemBytes = smem;
    cfg.stream = 0;
    cfg.attrs = &attr;
    cfg.numAttrs = 1;
    cudaLaunchKernelExC(&cfg, fn, args);
}

extern "C" void kernel_launch(void* const* d_in, const int* in_sizes, int n_in,
                              void* d_out, int out_size) {
    const float* x        = (const float*)d_in[0];
    const float* W_reduce = (const float*)d_in[1];
    const float* b_reduce = (const float*)d_in[2];
    const float* W_span   = (const float*)d_in[3];
    const float* b_span   = (const float*)d_in[4];
    float* out = (float*)d_out;

    cudaFuncSetAttribute(ker_fold, cudaFuncAttributeMaxDynamicSharedMemorySize, KF_SMEM);
    cudaFuncSetAttribute(inv_mma,  cudaFuncAttributeMaxDynamicSharedMemorySize, SMEM_INV);

    fuse_weights<<<RROWS * 4, 256>>>(W_reduce, b_reduce, W_span, b_span);

    {
        void* args[] = {(void*)&x};
        launch_pdl((const void*)ker_fold, dim3(HWD, B_), dim3(384), KF_SMEM, args);
    }
    {
        void* args[] = {(void*)&x, (void*)&out};
        launch_pdl((const void*)inv_mma, dim3(4, G_, B_), dim3(256), SMEM_INV, args);
    }
}

// round 16
// speedup vs baseline: 1.0140x; 1.0140x over previous
#include <cuda_runtime.h>
#include <cuda_fp16.h>
#include <cstdint>

// Problem constants
#define CH      256
#define G_      16
#define RROWS   144
#define RED_CH  128
#define B_      8
#define HWD     64
#define HW      4096

// ---------------- mma.sync / async helpers -----------------------------------
__device__ __forceinline__ uint32_t smem_u32(const void* p) {
    uint32_t a;
    asm("{ .reg .u64 t; cvta.to.shared.u64 t, %1; cvt.u32.u64 %0, t; }" : "=r"(a) : "l"(p));
    return a;
}
__device__ __forceinline__ void ldm_x4(uint32_t& r0, uint32_t& r1, uint32_t& r2,
                                       uint32_t& r3, uint32_t addr) {
    asm volatile("ldmatrix.sync.aligned.m8n8.x4.shared.b16 {%0,%1,%2,%3}, [%4];"
        : "=r"(r0), "=r"(r1), "=r"(r2), "=r"(r3) : "r"(addr));
}
__device__ __forceinline__ void ldm_x4t(uint32_t& r0, uint32_t& r1, uint32_t& r2,
                                        uint32_t& r3, uint32_t addr) {
    asm volatile("ldmatrix.sync.aligned.m8n8.x4.trans.shared.b16 {%0,%1,%2,%3}, [%4];"
        : "=r"(r0), "=r"(r1), "=r"(r2), "=r"(r3) : "r"(addr));
}
__device__ __forceinline__ void mma_f16(float* c, const uint32_t* a, const uint32_t* b) {
    asm volatile("mma.sync.aligned.m16n8k16.row.col.f32.f16.f16.f32 "
        "{%0,%1,%2,%3}, {%4,%5,%6,%7}, {%8,%9}, {%0,%1,%2,%3};"
        : "+f"(c[0]), "+f"(c[1]), "+f"(c[2]), "+f"(c[3])
        : "r"(a[0]), "r"(a[1]), "r"(a[2]), "r"(a[3]), "r"(b[0]), "r"(b[1]));
}
__device__ __forceinline__ void fsplit2(float a, float b, uint32_t& hi, uint32_t& lo) {
    __half2 h = __floats2half2_rn(a, b);
    hi = *reinterpret_cast<uint32_t*>(&h);
    float ra = a - __half2float(__low2half(h));
    float rb = b - __half2float(__high2half(h));
    __half2 l = __floats2half2_rn(ra, rb);
    lo = *reinterpret_cast<uint32_t*>(&l);
}
__device__ __forceinline__ uint32_t fpack2(float a, float b) {
    __half2 h = __floats2half2_rn(a, b);
    return *reinterpret_cast<uint32_t*>(&h);
}
__device__ __forceinline__ void cp16(uint32_t sdst, const void* gsrc) {
    asm volatile("cp.async.cg.shared.global [%0], [%1], 16;" :: "r"(sdst), "l"(gsrc));
}
#define CP_COMMIT() asm volatile("cp.async.commit_group;" ::: "memory")
#define CP_WAIT0()  asm volatile("cp.async.wait_group 0;" ::: "memory")

// ---------------- device scratch (pre-split fp16) ----------------------------
__device__ uint4 g_WcH4[RROWS * 32];          // Wc ah: 144 x 256 fp16
__device__ uint4 g_WcL4[RROWS * 32];          // Wc al
__device__ uint4 g_KpH4[B_ * G_ * 64 * 24];   // A' ah per (b,g): 64 x 192, 384 B/row
__device__ uint4 g_KpL4[B_ * G_ * 64 * 24];   // A' al
__device__ float g_bc[RROWS];

// ---------------- kernel A: fuse weights, 8-way k-split (R14 shape) ----------
__global__ __launch_bounds__(1024) void fuse_weights(
        const float* __restrict__ W_reduce, const float* __restrict__ b_reduce,
        const float* __restrict__ W_span,   const float* __restrict__ b_span) {
    __shared__ float ws[RED_CH];
    __shared__ float2 ps[1024];
    const int r   = blockIdx.x;
    const int tid = threadIdx.x;
    if (tid < RED_CH) ws[tid] = W_span[r * RED_CH + tid];
    __syncthreads();

    const int c2 = tid & 127;
    const int o0 = (tid >> 7) * 16;
    const float2* Wr2 = (const float2*)W_reduce;
    float s0 = 0.f, s1 = 0.f;
    #pragma unroll
    for (int o = o0; o < o0 + 16; o++) {
        const float2 w = Wr2[o * 128 + c2];
        const float a = ws[o];
        s0 += a * w.x;
        s1 += a * w.y;
    }
    ps[tid] = make_float2(s0, s1);
    __syncthreads();

    if (tid < 128) {
        s0 = 0.f; s1 = 0.f;
        #pragma unroll
        for (int p = 0; p < 8; p++) {
            float2 t = ps[tid + p * 128];
            s0 += t.x; s1 += t.y;
        }
        uint32_t hi, lo;
        fsplit2(s0, s1, hi, lo);
        ((uint32_t*)g_WcH4)[r * 128 + tid] = hi;
        ((uint32_t*)g_WcL4)[r * 128 + tid] = lo;
    }
    if (tid < 32) {
        float s = 0.f;
        #pragma unroll
        for (int o = tid; o < RED_CH; o += 32) s += ws[o] * b_reduce[o];
        #pragma unroll
        for (int d = 16; d > 0; d >>= 1) s += __shfl_xor_sync(0xffffffffu, s, d);
        if (tid == 0) g_bc[r] = s + b_span[r];
    }
    cudaTriggerProgrammaticLaunchCompletion();
}

// ---------------- kernel B: ker GEMM + fold; kt0 B staged pre-gridsync -------
#define KSTR   144
#define KF_AH  0
#define KF_AL  20736
#define KF_B   41472          // x single fp16: 64 x 144B
#define KF_BC  50688
#define KF_SMEM (KF_BC + 576)

__global__ __launch_bounds__(384, 2) void ker_fold(const float* __restrict__ x) {
    extern __shared__ char smem[];
    const uint32_t sb = smem_u32(smem);
    float* sbc = (float*)(smem + KF_BC);
    const int i0 = blockIdx.x;
    const int b  = blockIdx.y;
    const int tid = threadIdx.x;
    const int wid = tid >> 5, lane = tid & 31;
    const int wm = wid % 3;           // M block of 48 rows
    const int wn = wid / 3;           // N block of 16 cols (0..3)
    const int r  = lane & 15, hh = lane >> 4;

    float acc[3][2][4];
    #pragma unroll
    for (int mt = 0; mt < 3; mt++)
        #pragma unroll
        for (int nt = 0; nt < 2; nt++)
            #pragma unroll
            for (int e = 0; e < 4; e++) acc[mt][nt][e] = 0.f;

    // ===== fuse-independent pre-sync region ==================================
    // load x(kt=0), convert + store B tile, prefetch x(kt=1) — all before
    // waiting on fuse_weights.
    float4 breg[3];
    #pragma unroll
    for (int it = 0; it < 3; it++) {
        const int e = tid + 384 * it;
        if (e < 1024) {
            const int c = e >> 4, f = e & 15;
            breg[it] = *(const float4*)&x[((size_t)b * CH + c) * HW + i0 * HWD + f * 4];
        }
    }
    #pragma unroll
    for (int it = 0; it < 3; it++) {
        const int e = tid + 384 * it;
        if (e < 1024) {
            const int c = e >> 4, f = e & 15;
            const float4 v = breg[it];
            *(uint2*)(smem + KF_B + c * KSTR + f * 8) =
                make_uint2(fpack2(v.x, v.y), fpack2(v.z, v.w));
        }
    }
    #pragma unroll
    for (int it = 0; it < 3; it++) {
        const int e = tid + 384 * it;
        if (e < 1024) {
            const int c = e >> 4, f = e & 15;
            breg[it] = *(const float4*)&x[((size_t)b * CH + 64 + c) * HW + i0 * HWD + f * 4];
        }
    }

    // ===== wait for fuse_weights' Wc/bc stores ===============================
    cudaGridDependencySynchronize();
    if (tid < RROWS) sbc[tid] = g_bc[tid];

    #pragma unroll 1
    for (int kt = 0; kt < 4; kt++) {
        __syncthreads();                 // B buffer free (prev MMA done); smem visible
        #pragma unroll
        for (int it = 0; it < 3; it++) {
            const int e = tid + 384 * it;
            const int row = e >> 3, q = e & 7;
            cp16(sb + KF_AH + row * KSTR + q * 16, &g_WcH4[row * 32 + kt * 8 + q]);
            cp16(sb + KF_AL + row * KSTR + q * 16, &g_WcL4[row * 32 + kt * 8 + q]);
        }
        CP_COMMIT();
        // convert breg (holds x(kt)) -> smem B; kt=0 was staged pre-sync
        if (kt > 0) {
            #pragma unroll
            for (int it = 0; it < 3; it++) {
                const int e = tid + 384 * it;
                if (e < 1024) {
                    const int c = e >> 4, f = e & 15;
                    const float4 v = breg[it];
                    *(uint2*)(smem + KF_B + c * KSTR + f * 8) =
                        make_uint2(fpack2(v.x, v.y), fpack2(v.z, v.w));
                }
            }
        }
        // prefetch x(kt+1); at kt=0 breg already holds x(1)
        if (kt >= 1 && kt < 3) {
            #pragma unroll
            for (int it = 0; it < 3; it++) {
                const int e = tid + 384 * it;
                if (e < 1024) {
                    const int c = e >> 4, f = e & 15;
                    breg[it] = *(const float4*)&x[((size_t)b * CH + (kt + 1) * 64 + c) * HW + i0 * HWD + f * 4];
                }
            }
        }
        CP_WAIT0();
        __syncthreads();

        #pragma unroll
        for (int kk = 0; kk < 4; kk++) {
            uint32_t bh[4];
            const uint32_t bb = sb + KF_B + (kk * 16 + r) * KSTR + wn * 32 + hh * 16;
            ldm_x4t(bh[0], bh[1], bh[2], bh[3], bb);
            #pragma unroll
            for (int mt = 0; mt < 3; mt++) {
                uint32_t ah[4], al[4];
                const uint32_t ab = sb + KF_AH + (wm * 48 + mt * 16 + r) * KSTR + kk * 32 + hh * 16;
                ldm_x4(ah[0], ah[1], ah[2], ah[3], ab);
                ldm_x4(al[0], al[1], al[2], al[3], ab + (KF_AL - KF_AH));
                #pragma unroll
                for (int nt = 0; nt < 2; nt++) {
                    mma_f16(acc[mt][nt], ah, &bh[2 * nt]);
                    mma_f16(acc[mt][nt], al, &bh[2 * nt]);
                }
            }
        }
    }

    // ---- spill ker (+bias) to smem fp32 [144][68] ---------------------------
    __syncthreads();
    float* Ys = (float*)smem;
    {
        const int gq = lane >> 2;
        const int cb = (lane & 3) * 2;
        #pragma unroll
        for (int mt = 0; mt < 3; mt++) {
            const int row = wm * 48 + mt * 16 + gq;
            const float b0 = sbc[row], b1 = sbc[row + 8];
            #pragma unroll
            for (int nt = 0; nt < 2; nt++) {
                const int col = wn * 16 + nt * 8 + cb;
                *(float2*)&Ys[row * 68 + col]       = make_float2(acc[mt][nt][0] + b0, acc[mt][nt][1] + b0);
                *(float2*)&Ys[(row + 8) * 68 + col] = make_float2(acc[mt][nt][2] + b1, acc[mt][nt][3] + b1);
            }
        }
    }
    __syncthreads();

    // ---- fold over ki, write A' transposed fp16-split -----------------------
    if (tid < 256) {
        const int g  = tid >> 4;
        const int ms = (tid & 15) * 4;
        const size_t arow = ((size_t)(b * G_ + g) * 64 + i0) * 384;
        #pragma unroll
        for (int kj = 0; kj < 3; kj++) {
            const float* y1 = Ys + (g * 9 + 3 + kj) * 68;
            const float* y0 = Ys + (g * 9 + kj) * 68;
            const float* y2 = Ys + (g * 9 + 6 + kj) * 68;
            float v[4];
            #pragma unroll
            for (int mm = 0; mm < 4; mm++) {
                const int m = ms + mm;
                float t = y1[m];
                if (m < 63) t += y0[m + 1];
                if (m > 0)  t += y2[m - 1];
                v[mm] = t;
            }
            uint32_t h0, l0, h1, l1;
            fsplit2(v[0], v[1], h0, l0);
            fsplit2(v[2], v[3], h1, l1);
            const uint32_t cb2 = (kj * 64 + ms) * 2;
            *(uint2*)((char*)g_KpH4 + arow + cb2) = make_uint2(h0, h1);
            *(uint2*)((char*)g_KpL4 + arow + cb2) = make_uint2(l0, l1);
        }
    }
    cudaTriggerProgrammaticLaunchCompletion();
}

// ---------------- kernel C: shifted-B GEMM, fp16 2-pass, 4 ch/CTA, PDL -------
#define IA_STR  400
#define I_AH    0
#define I_AL    25600
#define I_B     51200          // B' single fp16: 192 x 144B
#define SMEM_INV 78848

__global__ __launch_bounds__(256, 2) void inv_mma(const float* __restrict__ x,
                                                  float* __restrict__ out) {
    extern __shared__ char smem[];
    const uint32_t sb = smem_u32(smem);
    const int cq = blockIdx.x, g = blockIdx.y, b = blockIdx.z;
    const int tid  = threadIdx.x;
    const int wid  = tid >> 5, lane = tid & 31;
    const int wm   = wid & 3;          // i quadrant (16 rows)
    const int wn   = wid >> 2;         // j half (32 cols)
    const int ch0  = g * 16 + cq * 4;
    const float* xbase = x + ((size_t)(b * CH) + ch0) * HW;

    int mArr[4], j0Arr[4];
    #pragma unroll
    for (int it = 0; it < 4; it++) {
        const int e = tid + 256 * it;
        mArr[it] = e >> 4;
        j0Arr[it] = (e & 15) << 2;
    }

    // prefetch x(channel 0) — independent of ker_fold; runs before grid sync
    float4 v[4]; float am1[4], a4[4];
    #pragma unroll
    for (int it = 0; it < 4; it++) {
        const float* row = xbase + mArr[it] * 64;
        v[it]  = *(const float4*)&row[j0Arr[it]];
        am1[it] = (j0Arr[it] > 0)  ? row[j0Arr[it] - 1] : 0.f;
        a4[it]  = (j0Arr[it] < 60) ? row[j0Arr[it] + 4] : 0.f;
    }

    // wait for ker_fold's Kp stores, then start the A' async copy
    cudaGridDependencySynchronize();
    {
        const uint4* KH = g_KpH4 + (size_t)(b * G_ + g) * 1536;
        const uint4* KL = g_KpL4 + (size_t)(b * G_ + g) * 1536;
        #pragma unroll
        for (int it = 0; it < 6; it++) {
            const int e = tid + 256 * it;
            const int row = e / 24, q = e - row * 24;
            cp16(sb + I_AH + row * IA_STR + q * 16, KH + e);
            cp16(sb + I_AL + row * IA_STR + q * 16, KL + e);
        }
        CP_COMMIT();
    }

    const int r  = lane & 15;
    const int hh = lane >> 4;
    const int gq = lane >> 2, cb = (lane & 3) * 2;
    const int i0 = wm * 16 + gq;

    #pragma unroll 1
    for (int cc = 0; cc < 4; cc++) {
        if (cc > 0) __syncthreads();
        // ---- build B'(cc): single fp16, 3 shifted copies ---------------------
        #pragma unroll
        for (int it = 0; it < 4; it++) {
            const int m = mArr[it], j0 = j0Arr[it];
            uint32_t p0 = fpack2(am1[it], v[it].x);
            uint32_t p1 = fpack2(v[it].x, v[it].y);
            uint32_t p2 = fpack2(v[it].y, v[it].z);
            uint32_t p3 = fpack2(v[it].z, v[it].w);
            uint32_t p4 = fpack2(v[it].w, a4[it]);
            const uint32_t cbyte = j0 * 2;
            *(uint2*)(smem + I_B + m * 144 + cbyte)         = make_uint2(p0, p2);
            *(uint2*)(smem + I_B + (64 + m) * 144 + cbyte)  = make_uint2(p1, p3);
            *(uint2*)(smem + I_B + (128 + m) * 144 + cbyte) = make_uint2(p2, p4);
        }
        if (cc == 0) CP_WAIT0();
        __syncthreads();

        // ---- prefetch x(cc+1) (hidden under MMA) -----------------------------
        if (cc < 3) {
            const float* xn = xbase + (cc + 1) * HW;
            #pragma unroll
            for (int it = 0; it < 4; it++) {
                const float* row = xn + mArr[it] * 64;
                v[it]  = *(const float4*)&row[j0Arr[it]];
                am1[it] = (j0Arr[it] > 0)  ? row[j0Arr[it] - 1] : 0.f;
                a4[it]  = (j0Arr[it] < 60) ? row[j0Arr[it] + 4] : 0.f;
            }
        }

        // ---- K=192 mma, fp16 2-pass -----------------------------------------
        float acc[4][4];
        #pragma unroll
        for (int nt = 0; nt < 4; nt++)
            #pragma unroll
            for (int e = 0; e < 4; e++) acc[nt][e] = 0.f;

        #pragma unroll
        for (int k = 0; k < 12; k++) {
            uint32_t ah[4], al[4];
            const uint32_t abase = sb + I_AH + (wm * 16 + r) * IA_STR + k * 32 + hh * 16;
            ldm_x4(ah[0], ah[1], ah[2], ah[3], abase);
            ldm_x4(al[0], al[1], al[2], al[3], abase + (I_AL - I_AH));
            uint32_t bh[4][2];
            #pragma unroll
            for (int ntp = 0; ntp < 2; ntp++) {
                const uint32_t bb = sb + I_B + (k * 16 + r) * 144 + wn * 64 + ntp * 32 + hh * 16;
                ldm_x4t(bh[2*ntp][0], bh[2*ntp][1], bh[2*ntp+1][0], bh[2*ntp+1][1], bb);
            }
            #pragma unroll
            for (int nt = 0; nt < 4; nt++) {
                mma_f16(acc[nt], ah, bh[nt]);
                mma_f16(acc[nt], al, bh[nt]);
            }
        }

        // ---- direct store -----------------------------------------------------
        float* op = out + ((size_t)(b * CH) + ch0 + cc) * HW;
        #pragma unroll
        for (int nt = 0; nt < 4; nt++) {
            const int j = wn * 32 + nt * 8 + cb;
            *(float2*)&op[i0 * 64 + j]       = make_float2(acc[nt][0], acc[nt][1]);
            *(float2*)&op[(i0 + 8) * 64 + j] = make_float2(acc[nt][2], acc[nt][3]);
        }
    }
}

// ---------------- launch ------------------------------------------------------
static void launch_pdl(const void* fn, dim3 grid, dim3 block, size_t smem,
                       void** args) {
    cudaLaunchAttribute attr;
    attr.id = cudaLaunchAttributeProgrammaticStreamSerialization;
    attr.val.programmaticStreamSerializationAllowed = 1;
    cudaLaunchConfig_t cfg{};
    cfg.gridDim = grid;
    cfg.blockDim = block;
    cfg.dynamicSmemBytes = smem;
    cfg.stream = 0;
    cfg.attrs = &attr;
    cfg.numAttrs = 1;
    cudaLaunchKernelExC(&cfg, fn, args);
}

extern "C" void kernel_launch(void* const* d_in, const int* in_sizes, int n_in,
                              void* d_out, int out_size) {
    const float* x        = (const float*)d_in[0];
    const float* W_reduce = (const float*)d_in[1];
    const float* b_reduce = (const float*)d_in[2];
    const float* W_span   = (const float*)d_in[3];
    const float* b_span   = (const float*)d_in[4];
    float* out = (float*)d_out;

    cudaFuncSetAttribute(ker_fold, cudaFuncAttributeMaxDynamicSharedMemorySize, KF_SMEM);
    cudaFuncSetAttribute(inv_mma,  cudaFuncAttributeMaxDynamicSharedMemorySize, SMEM_INV);

    fuse_weights<<<RROWS, 1024>>>(W_reduce, b_reduce, W_span, b_span);

    {
        void* args[] = {(void*)&x};
        launch_pdl((const void*)ker_fold, dim3(HWD, B_), dim3(384), KF_SMEM, args);
    }
    {
        void* args[] = {(void*)&x, (void*)&out};
        launch_pdl((const void*)inv_mma, dim3(4, G_, B_), dim3(256), SMEM_INV, args);
    }
}